// round 8
// baseline (speedup 1.0000x reference)
#include <cuda_runtime.h>
#include <cuda_bf16.h>
#include <cstdint>
#include <cstddef>

#define NATOM 100000
#define NCL   25000
#define EA    600000
#define EC    100000
#define EB    100000
#define HD    128
#define PD    256
#define BN_EPS 1e-5f

// ---------------- scratch (static device memory; no allocs allowed) ----------------
__device__ float g_agg_atom[(size_t)NATOM * HD];
__device__ float g_agg_cl[(size_t)NCL * HD];
__device__ float g_aggm_c2a[(size_t)NATOM * HD];
__device__ float g_cnt_c2a[NATOM];
__device__ float g_aggm_a2c[(size_t)NCL * HD];
__device__ float g_cnt_a2c[NCL];
__device__ float g_pre_atom[(size_t)NATOM * PD];
__device__ float g_pre_cl[(size_t)NCL * PD];
__device__ float g_S_atom[(size_t)NATOM * PD];
__device__ float g_S_cl[(size_t)NCL * PD];
__device__ float g_stats_atom[2 * PD];
__device__ float g_stats_cl[2 * PD];
__device__ float g_scale_atom[PD];
__device__ float g_shift_atom[PD];
__device__ float g_scale_cl[PD];
__device__ float g_shift_cl[PD];

// transposed + hi/lo-split weights, bf16:  [n][k] row-major per matrix
#define OFF_GA 0
#define OFF_GC 32768
#define OFF_SA 65536
#define OFF_SC 131072
#define OFF_MA 196608
#define OFF_MC 229376
__device__ __nv_bfloat16 g_Bt_hi[262144];
__device__ __nv_bfloat16 g_Bt_lo[262144];

// ---------------- helpers ---------------------------------------------------------
__device__ __forceinline__ uint32_t smem_u32(const void* p) {
    uint32_t a;
    asm("{ .reg .u64 t; cvta.to.shared.u64 t, %1; cvt.u32.u64 %0, t; }" : "=r"(a) : "l"(p));
    return a;
}
__device__ __forceinline__ void ldm_x4(uint32_t* r, uint32_t addr) {
    asm volatile("ldmatrix.sync.aligned.m8n8.x4.shared.b16 {%0,%1,%2,%3}, [%4];"
                 : "=r"(r[0]), "=r"(r[1]), "=r"(r[2]), "=r"(r[3]) : "r"(addr));
}
__device__ __forceinline__ void mma16816(float* c, const uint32_t* a, const uint32_t* b) {
    asm volatile("mma.sync.aligned.m16n8k16.row.col.f32.bf16.bf16.f32 "
                 "{%0,%1,%2,%3}, {%4,%5,%6,%7}, {%8,%9}, {%0,%1,%2,%3};"
                 : "+f"(c[0]), "+f"(c[1]), "+f"(c[2]), "+f"(c[3])
                 : "r"(a[0]), "r"(a[1]), "r"(a[2]), "r"(a[3]), "r"(b[0]), "r"(b[1]));
}
__device__ __forceinline__ void red_v4(float* p, float a, float b, float c, float d) {
    asm volatile("red.global.add.v4.f32 [%0], {%1,%2,%3,%4};"
                 :: "l"(p), "f"(a), "f"(b), "f"(c), "f"(d) : "memory");
}
__device__ __forceinline__ void cp16(uint32_t s, const void* g) {
    asm volatile("cp.async.cg.shared.global [%0], [%1], 16;" :: "r"(s), "l"(g));
}
__device__ __forceinline__ uint32_t pack_lo_bf16(float lox, float loy) {
    uint32_t r;
    asm("cvt.rn.bf16x2.f32 %0, %1, %2;" : "=r"(r) : "f"(loy), "f"(lox));
    return r;
}

// ---------------- edge scatter kernels: 2 edges per warp (MLP x2) -----------------
__global__ void gine_scatter(const float* __restrict__ x, const float* __restrict__ ea,
                             const int* __restrict__ ei, int E, float* __restrict__ agg) {
    int warp = (blockIdx.x * blockDim.x + threadIdx.x) >> 5;
    int lane = threadIdx.x & 31;
    int e0 = warp * 2;
    if (e0 >= E) return;
    int e1 = e0 + 1;                       // E is even for all graphs here
    int src0 = ei[e0], src1 = ei[e1];
    int dst0 = ei[E + e0], dst1 = ei[E + e1];
    float4 xv0 = reinterpret_cast<const float4*>(x + (size_t)src0 * HD)[lane];
    float4 xv1 = reinterpret_cast<const float4*>(x + (size_t)src1 * HD)[lane];
    float4 ev0 = reinterpret_cast<const float4*>(ea + (size_t)e0 * HD)[lane];
    float4 ev1 = reinterpret_cast<const float4*>(ea + (size_t)e1 * HD)[lane];
    red_v4(agg + (size_t)dst0 * HD + lane * 4,
           fmaxf(xv0.x + ev0.x, 0.0f), fmaxf(xv0.y + ev0.y, 0.0f),
           fmaxf(xv0.z + ev0.z, 0.0f), fmaxf(xv0.w + ev0.w, 0.0f));
    red_v4(agg + (size_t)dst1 * HD + lane * 4,
           fmaxf(xv1.x + ev1.x, 0.0f), fmaxf(xv1.y + ev1.y, 0.0f),
           fmaxf(xv1.z + ev1.z, 0.0f), fmaxf(xv1.w + ev1.w, 0.0f));
}

__global__ void sage_scatter(const float* __restrict__ xsrc, const int* __restrict__ ei,
                             int E, float* __restrict__ aggm, float* __restrict__ cnt) {
    int warp = (blockIdx.x * blockDim.x + threadIdx.x) >> 5;
    int lane = threadIdx.x & 31;
    int e0 = warp * 2;
    if (e0 >= E) return;
    int e1 = e0 + 1;
    int src0 = ei[e0], src1 = ei[e1];
    int dst0 = ei[E + e0], dst1 = ei[E + e1];
    float4 xv0 = reinterpret_cast<const float4*>(xsrc + (size_t)src0 * HD)[lane];
    float4 xv1 = reinterpret_cast<const float4*>(xsrc + (size_t)src1 * HD)[lane];
    red_v4(aggm + (size_t)dst0 * HD + lane * 4, xv0.x, xv0.y, xv0.z, xv0.w);
    red_v4(aggm + (size_t)dst1 * HD + lane * 4, xv1.x, xv1.y, xv1.z, xv1.w);
    if (lane == 0) {
        atomicAdd(&cnt[dst0], 1.0f);
        atomicAdd(&cnt[dst1], 1.0f);
    }
}

// ---------------- BN finalize (both sets, one launch) -----------------------------
__global__ void bn_finalize2(const float* __restrict__ sa, const float* __restrict__ sc,
                             const float* __restrict__ ga, const float* __restrict__ ba,
                             const float* __restrict__ gc, const float* __restrict__ bc,
                             float* __restrict__ scaleA, float* __restrict__ shiftA,
                             float* __restrict__ scaleC, float* __restrict__ shiftC) {
    int c = threadIdx.x & 255;
    if (threadIdx.x < 256) {
        float invM = 1.0f / NATOM;
        float mu = sa[c] * invM;
        float var = sa[PD + c] * invM - mu * mu;
        float s = ga[c] * rsqrtf(var + BN_EPS);
        scaleA[c] = s;
        shiftA[c] = ba[c] - mu * s;
    } else {
        float invM = 1.0f / NCL;
        float mu = sc[c] * invM;
        float var = sc[PD + c] * invM - mu * mu;
        float s = gc[c] * rsqrtf(var + BN_EPS);
        scaleC[c] = s;
        shiftC[c] = bc[c] - mu * s;
    }
}

// ---------------- fused weight transpose + hi/lo split (one launch) ---------------
struct WsplitArgs { const float* src[8]; };
__constant__ int c_ws_N[8]     = {256, 256, 256, 256, 256, 256, 128, 128};
__constant__ int c_ws_koff[8]  = {0, 0, 0, 128, 0, 128, 0, 0};
__constant__ int c_ws_kout[8]  = {128, 128, 256, 256, 256, 256, 256, 256};
__constant__ int c_ws_doff[8]  = {OFF_GA, OFF_GC, OFF_SA, OFF_SA, OFF_SC, OFF_SC, OFF_MA, OFF_MC};

__global__ void wsplit_all(WsplitArgs args,
                           __nv_bfloat16* __restrict__ oh, __nv_bfloat16* __restrict__ ol) {
    int i = blockIdx.x * blockDim.x + threadIdx.x;   // 0 .. 262143
    int seg = i >> 15;
    int w = i & 32767;
    int N = c_ws_N[seg];
    int k = w / N, n = w - k * N;
    float v = args.src[seg][w];
    uint32_t bits = __float_as_uint(v);
    uint32_t hbits = bits & 0xFFFF0000u;
    float lo = v - __uint_as_float(hbits);
    size_t o = (size_t)n * c_ws_kout[seg] + c_ws_koff[seg] + k + c_ws_doff[seg];
    oh[o] = __ushort_as_bfloat16((unsigned short)(hbits >> 16));
    ol[o] = __float2bfloat16(lo);
}

// ---------------- mma.sync split-bf16 GEMM with fused A-transforms ----------------
// per-CTA tile: 128 rows x NTILE cols; BLOCK threads.
// mode 0 (GINE):  A = (1+eps)*A0 + A1                    (K=128)  [+ fused col stats]
// mode 1 (SAGE):  A = [A0/max(cnt,1) | A1]               (K=256)
// mode 2 (MERGE): A = relu(A0*scale+shift) + A1          (K=256)
#define SMO_AH   1024
#define SMO_AL   33792
#define SMO_BH   66560

template <int K, int NTILE, int BLOCK>
__global__ __launch_bounds__(BLOCK)
void hmma_gemm(int mode, int M,
               const float* __restrict__ A0, const float* __restrict__ A1,
               const float* __restrict__ aux0, const float* __restrict__ aux1,
               const __nv_bfloat16* __restrict__ Bt_hi,
               const __nv_bfloat16* __restrict__ Bt_lo,
               const float* __restrict__ bias0, const float* __restrict__ bias1,
               const float* __restrict__ epsPtr, float* __restrict__ statsG,
               float* __restrict__ C, int ldc) {
    constexpr int WARPS = BLOCK / 32;
    constexpr int WN = NTILE / 64;        // warps along n (64 cols each)
    constexpr int WM = WARPS / WN;        // warps along m
    constexpr int RPW = 128 / WM;         // rows per warp
    constexpr int MT = RPW / 16;          // 16-row m-tiles per warp
    constexpr int SMO_BL = SMO_BH + NTILE * 256;
    extern __shared__ char smem[];
    uint32_t sb = smem_u32(smem);
    const int tid = threadIdx.x;
    const int wid = tid >> 5;
    const int lid = tid & 31;
    const int wm = wid % WM;
    const int wn = wid / WM;
    const int m0 = blockIdx.x * 128;

    float* bias_s = reinterpret_cast<float*>(smem);
    if (tid < NTILE) {
        float b = bias0[tid];
        if (bias1) b += bias1[tid];
        bias_s[tid] = b;
    }

    const float ef = (mode == 0) ? 1.0f + *epsPtr : 1.0f;

    float acc[MT][8][4];
#pragma unroll
    for (int mt = 0; mt < MT; mt++)
#pragma unroll
        for (int nt = 0; nt < 8; nt++)
#pragma unroll
            for (int j = 0; j < 4; j++) acc[mt][nt][j] = 0.0f;

    for (int kk = 0; kk < K; kk += 128) {
        // ---- B tile via cp.async: NTILE n-rows x 128 k bf16 (hi & lo) ----
#pragma unroll
        for (int it = 0; it < NTILE * 16 / BLOCK; it++) {
            int idx = tid + it * BLOCK;
            int n = idx >> 4;
            int ch = idx & 15;
            uint32_t off = n * 256 + ((ch ^ (n & 7)) << 4);
            cp16(sb + SMO_BH + off, Bt_hi + (size_t)n * K + kk + ch * 8);
            cp16(sb + SMO_BL + off, Bt_lo + (size_t)n * K + kk + ch * 8);
        }
        asm volatile("cp.async.commit_group;" ::: "memory");

        // ---- A tile: 128 rows x 128 fp32 -> transform -> truncation split ----
#pragma unroll
        for (int it = 0; it < 4096 / BLOCK; it++) {
            int idx = tid + it * BLOCK;        // 0..4095 float4s
            int r = idx >> 5;
            int c4 = (idx & 31) * 4;
            int gr = m0 + r;
            int gk = kk + c4;
            float4 v = make_float4(0.f, 0.f, 0.f, 0.f);
            if (gr < M) {
                if (mode == 0) {
                    float4 a = *reinterpret_cast<const float4*>(A0 + (size_t)gr * 128 + gk);
                    float4 g = *reinterpret_cast<const float4*>(A1 + (size_t)gr * 128 + gk);
                    v.x = fmaf(ef, a.x, g.x); v.y = fmaf(ef, a.y, g.y);
                    v.z = fmaf(ef, a.z, g.z); v.w = fmaf(ef, a.w, g.w);
                } else if (mode == 1) {
                    if (gk < 128) {
                        float4 a = *reinterpret_cast<const float4*>(A0 + (size_t)gr * 128 + gk);
                        float inv = __frcp_rn(fmaxf(aux0[gr], 1.0f));
                        v.x = a.x * inv; v.y = a.y * inv; v.z = a.z * inv; v.w = a.w * inv;
                    } else {
                        v = *reinterpret_cast<const float4*>(A1 + (size_t)gr * 128 + (gk - 128));
                    }
                } else {
                    float4 p = *reinterpret_cast<const float4*>(A0 + (size_t)gr * 256 + gk);
                    float4 q = *reinterpret_cast<const float4*>(A1 + (size_t)gr * 256 + gk);
                    float4 s = *reinterpret_cast<const float4*>(aux0 + gk);
                    float4 hh = *reinterpret_cast<const float4*>(aux1 + gk);
                    v.x = fmaxf(fmaf(p.x, s.x, hh.x), 0.f) + q.x;
                    v.y = fmaxf(fmaf(p.y, s.y, hh.y), 0.f) + q.y;
                    v.z = fmaxf(fmaf(p.z, s.z, hh.z), 0.f) + q.z;
                    v.w = fmaxf(fmaf(p.w, s.w, hh.w), 0.f) + q.w;
                }
            }
            uint32_t bx = __float_as_uint(v.x), by = __float_as_uint(v.y);
            uint32_t bz = __float_as_uint(v.z), bw = __float_as_uint(v.w);
            uint2 hp, lp;
            hp.x = __byte_perm(bx, by, 0x7632);
            hp.y = __byte_perm(bz, bw, 0x7632);
            lp.x = pack_lo_bf16(v.x - __uint_as_float(bx & 0xFFFF0000u),
                                v.y - __uint_as_float(by & 0xFFFF0000u));
            lp.y = pack_lo_bf16(v.z - __uint_as_float(bz & 0xFFFF0000u),
                                v.w - __uint_as_float(bw & 0xFFFF0000u));
            uint32_t off = r * 256 + (((c4 >> 3) ^ (r & 7)) << 4) + ((c4 & 4) << 1);
            *reinterpret_cast<uint2*>(smem + SMO_AH + off) = hp;
            *reinterpret_cast<uint2*>(smem + SMO_AL + off) = lp;
        }
        asm volatile("cp.async.wait_group 0;" ::: "memory");
        __syncthreads();

        // ---- compute: 8 k-steps of 16 ----
        const int arow = wm * RPW + (lid & 15);
        const int akp = lid >> 4;
        const int bn = wn * 64 + (lid & 7) + ((lid >> 4) << 3);
        const int bkp = (lid >> 3) & 1;
#pragma unroll
        for (int ks = 0; ks < 8; ks++) {
            uint32_t ah[MT][4], al[MT][4];
#pragma unroll
            for (int mt = 0; mt < MT; mt++) {
                int r = arow + mt * 16;
                uint32_t ch = (uint32_t)((ks * 2 + akp) ^ (r & 7));
                uint32_t off = r * 256 + (ch << 4);
                ldm_x4(ah[mt], sb + SMO_AH + off);
                ldm_x4(al[mt], sb + SMO_AL + off);
            }
#pragma unroll
            for (int np = 0; np < 4; np++) {
                int n = bn + np * 16;
                uint32_t ch = (uint32_t)((ks * 2 + bkp) ^ (n & 7));
                uint32_t off = n * 256 + (ch << 4);
                uint32_t bh[4], bl[4];
                ldm_x4(bh, sb + SMO_BH + off);
                ldm_x4(bl, sb + SMO_BL + off);
#pragma unroll
                for (int mt = 0; mt < MT; mt++) {
#pragma unroll
                    for (int sn = 0; sn < 2; sn++) {
                        float* c = acc[mt][np * 2 + sn];
                        mma16816(c, ah[mt], bh + sn * 2);
                        mma16816(c, ah[mt], bl + sn * 2);
                        mma16816(c, al[mt], bh + sn * 2);
                    }
                }
            }
        }
        __syncthreads();
    }

    // ---- epilogue: store + optional fused column stats ----
    const int g = lid >> 2;
    const int tig = lid & 3;
#pragma unroll
    for (int nt = 0; nt < 8; nt++) {
        int nl = wn * 64 + nt * 8 + 2 * tig;
        float b0 = bias_s[nl], b1 = bias_s[nl + 1];
        float s0 = 0.f, s1 = 0.f, q0 = 0.f, q1 = 0.f;
#pragma unroll
        for (int mt = 0; mt < MT; mt++) {
            int m = m0 + wm * RPW + mt * 16 + g;
            if (m < M) {
                float ox = acc[mt][nt][0] + b0, oy = acc[mt][nt][1] + b1;
                *reinterpret_cast<float2*>(C + (size_t)m * ldc + nl) = make_float2(ox, oy);
                s0 += ox; s1 += oy; q0 += ox * ox; q1 += oy * oy;
            }
            if (m + 8 < M) {
                float ox = acc[mt][nt][2] + b0, oy = acc[mt][nt][3] + b1;
                *reinterpret_cast<float2*>(C + (size_t)(m + 8) * ldc + nl) = make_float2(ox, oy);
                s0 += ox; s1 += oy; q0 += ox * ox; q1 += oy * oy;
            }
        }
        if (statsG) {
#pragma unroll
            for (int d = 4; d < 32; d <<= 1) {
                s0 += __shfl_xor_sync(0xFFFFFFFFu, s0, d);
                s1 += __shfl_xor_sync(0xFFFFFFFFu, s1, d);
                q0 += __shfl_xor_sync(0xFFFFFFFFu, q0, d);
                q1 += __shfl_xor_sync(0xFFFFFFFFu, q1, d);
            }
            if (g == 0) {
                atomicAdd(statsG + nl, s0);
                atomicAdd(statsG + nl + 1, s1);
                atomicAdd(statsG + PD + nl, q0);
                atomicAdd(statsG + PD + nl + 1, q1);
            }
        }
    }
}

// -----------------------------------------------------------------------------------
extern "C" void kernel_launch(void* const* d_in, const int* in_sizes, int n_in,
                              void* d_out, int out_size) {
    const float* x         = (const float*)d_in[0];
    const float* edge_attr = (const float*)d_in[1];
    const float* x_cl      = (const float*)d_in[2];
    const float* c2c_ea    = (const float*)d_in[3];

    int pbase, ebase;
    if (in_sizes[4] == 2 * EA) { ebase = 4; pbase = 8; }
    else                       { pbase = 4; ebase = 26; }

    const int* ei_a   = (const int*)d_in[ebase + 0];
    const int* ei_c2c = (const int*)d_in[ebase + 1];
    const int* ei_a2c = (const int*)d_in[ebase + 2];
    const int* ei_c2a = (const int*)d_in[ebase + 3];

    const float* atom_eps   = (const float*)d_in[pbase + 0];
    const float* atom_W     = (const float*)d_in[pbase + 1];
    const float* atom_b     = (const float*)d_in[pbase + 2];
    const float* atom_gamma = (const float*)d_in[pbase + 3];
    const float* atom_beta  = (const float*)d_in[pbase + 4];
    const float* cl_eps     = (const float*)d_in[pbase + 5];
    const float* cl_W       = (const float*)d_in[pbase + 6];
    const float* cl_b       = (const float*)d_in[pbase + 7];
    const float* cl_gamma   = (const float*)d_in[pbase + 8];
    const float* cl_beta    = (const float*)d_in[pbase + 9];
    const float* a2c_Wl     = (const float*)d_in[pbase + 10];
    const float* a2c_bl     = (const float*)d_in[pbase + 11];
    const float* a2c_Wr     = (const float*)d_in[pbase + 12];
    const float* a2c_br     = (const float*)d_in[pbase + 13];
    const float* c2a_Wl     = (const float*)d_in[pbase + 14];
    const float* c2a_bl     = (const float*)d_in[pbase + 15];
    const float* c2a_Wr     = (const float*)d_in[pbase + 16];
    const float* c2a_br     = (const float*)d_in[pbase + 17];
    const float* merge_atom_W = (const float*)d_in[pbase + 18];
    const float* merge_atom_b = (const float*)d_in[pbase + 19];
    const float* merge_cl_W   = (const float*)d_in[pbase + 20];
    const float* merge_cl_b   = (const float*)d_in[pbase + 21];

    float* out = (float*)d_out;

    float *p_agg_atom, *p_agg_cl, *p_aggm_c2a, *p_cnt_c2a, *p_aggm_a2c, *p_cnt_a2c;
    float *p_pre_atom, *p_pre_cl, *p_S_atom, *p_S_cl;
    float *p_stats_atom, *p_stats_cl, *p_scale_atom, *p_shift_atom, *p_scale_cl, *p_shift_cl;
    __nv_bfloat16 *p_Bt_hi, *p_Bt_lo;
    cudaGetSymbolAddress((void**)&p_agg_atom, g_agg_atom);
    cudaGetSymbolAddress((void**)&p_agg_cl, g_agg_cl);
    cudaGetSymbolAddress((void**)&p_aggm_c2a, g_aggm_c2a);
    cudaGetSymbolAddress((void**)&p_cnt_c2a, g_cnt_c2a);
    cudaGetSymbolAddress((void**)&p_aggm_a2c, g_aggm_a2c);
    cudaGetSymbolAddress((void**)&p_cnt_a2c, g_cnt_a2c);
    cudaGetSymbolAddress((void**)&p_pre_atom, g_pre_atom);
    cudaGetSymbolAddress((void**)&p_pre_cl, g_pre_cl);
    cudaGetSymbolAddress((void**)&p_S_atom, g_S_atom);
    cudaGetSymbolAddress((void**)&p_S_cl, g_S_cl);
    cudaGetSymbolAddress((void**)&p_stats_atom, g_stats_atom);
    cudaGetSymbolAddress((void**)&p_stats_cl, g_stats_cl);
    cudaGetSymbolAddress((void**)&p_scale_atom, g_scale_atom);
    cudaGetSymbolAddress((void**)&p_shift_atom, g_shift_atom);
    cudaGetSymbolAddress((void**)&p_scale_cl, g_scale_cl);
    cudaGetSymbolAddress((void**)&p_shift_cl, g_shift_cl);
    cudaGetSymbolAddress((void**)&p_Bt_hi, g_Bt_hi);
    cudaGetSymbolAddress((void**)&p_Bt_lo, g_Bt_lo);

    cudaMemsetAsync(p_agg_atom, 0, (size_t)NATOM * HD * 4, 0);
    cudaMemsetAsync(p_agg_cl, 0, (size_t)NCL * HD * 4, 0);
    cudaMemsetAsync(p_aggm_c2a, 0, (size_t)NATOM * HD * 4, 0);
    cudaMemsetAsync(p_cnt_c2a, 0, (size_t)NATOM * 4, 0);
    cudaMemsetAsync(p_aggm_a2c, 0, (size_t)NCL * HD * 4, 0);
    cudaMemsetAsync(p_cnt_a2c, 0, (size_t)NCL * 4, 0);
    cudaMemsetAsync(p_stats_atom, 0, 2 * PD * 4, 0);
    cudaMemsetAsync(p_stats_cl, 0, 2 * PD * 4, 0);

    const int SMEM_256 = 66560 + 256 * 256 * 2;  // 197632
    const int SMEM_128 = 66560 + 128 * 256 * 2;  // 132096
    cudaFuncSetAttribute((const void*)hmma_gemm<128, 256, 512>,
                         cudaFuncAttributeMaxDynamicSharedMemorySize, SMEM_256);
    cudaFuncSetAttribute((const void*)hmma_gemm<256, 256, 512>,
                         cudaFuncAttributeMaxDynamicSharedMemorySize, SMEM_256);
    cudaFuncSetAttribute((const void*)hmma_gemm<256, 128, 512>,
                         cudaFuncAttributeMaxDynamicSharedMemorySize, SMEM_128);

    // ---- fused weight transpose + split (one launch) ----
    {
        WsplitArgs wa;
        wa.src[0] = atom_W;  wa.src[1] = cl_W;
        wa.src[2] = c2a_Wl;  wa.src[3] = c2a_Wr;
        wa.src[4] = a2c_Wl;  wa.src[5] = a2c_Wr;
        wa.src[6] = merge_atom_W; wa.src[7] = merge_cl_W;
        wsplit_all<<<1024, 256>>>(wa, p_Bt_hi, p_Bt_lo);
    }

    // ---- scatter passes (2 edges per warp) ----
    gine_scatter<<<(EA / 2 * 32 + 255) / 256, 256>>>(x, edge_attr, ei_a, EA, p_agg_atom);
    gine_scatter<<<(EC / 2 * 32 + 255) / 256, 256>>>(x_cl, c2c_ea, ei_c2c, EC, p_agg_cl);
    sage_scatter<<<(EB / 2 * 32 + 255) / 256, 256>>>(x, ei_a2c, EB, p_aggm_a2c, p_cnt_a2c);
    sage_scatter<<<(EB / 2 * 32 + 255) / 256, 256>>>(x_cl, ei_c2a, EB, p_aggm_c2a, p_cnt_c2a);

    const int GA = (NATOM + 127) / 128;  // 782
    const int GC = (NCL + 127) / 128;    // 196

    // ---- GINE GEMMs (pre-BN, fused column stats): [M,128]@[128,256] ----
    hmma_gemm<128, 256, 512><<<GA, 512, SMEM_256>>>(
        0, NATOM, x, p_agg_atom, nullptr, nullptr,
        p_Bt_hi + OFF_GA, p_Bt_lo + OFF_GA, atom_b, nullptr, atom_eps, p_stats_atom,
        p_pre_atom, 256);
    hmma_gemm<128, 256, 512><<<GC, 512, SMEM_256>>>(
        0, NCL, x_cl, p_agg_cl, nullptr, nullptr,
        p_Bt_hi + OFF_GC, p_Bt_lo + OFF_GC, cl_b, nullptr, cl_eps, p_stats_cl,
        p_pre_cl, 256);

    bn_finalize2<<<1, 512>>>(p_stats_atom, p_stats_cl, atom_gamma, atom_beta,
                             cl_gamma, cl_beta, p_scale_atom, p_shift_atom,
                             p_scale_cl, p_shift_cl);

    // ---- SAGE GEMMs: [mean | x_dst]@[Wl;Wr]+bl+br -> [M,256] ----
    hmma_gemm<256, 256, 512><<<GA, 512, SMEM_256>>>(
        1, NATOM, p_aggm_c2a, x, p_cnt_c2a, nullptr,
        p_Bt_hi + OFF_SA, p_Bt_lo + OFF_SA, c2a_bl, c2a_br, nullptr, nullptr,
        p_S_atom, 256);
    hmma_gemm<256, 256, 512><<<GC, 512, SMEM_256>>>(
        1, NCL, p_aggm_a2c, x_cl, p_cnt_a2c, nullptr,
        p_Bt_hi + OFF_SC, p_Bt_lo + OFF_SC, a2c_bl, a2c_br, nullptr, nullptr,
        p_S_cl, 256);

    // ---- merge GEMMs (fused BN+ReLU+residual) -> final output [M,128] ----
    hmma_gemm<256, 128, 512><<<GA, 512, SMEM_128>>>(
        2, NATOM, p_pre_atom, p_S_atom, p_scale_atom, p_shift_atom,
        p_Bt_hi + OFF_MA, p_Bt_lo + OFF_MA, merge_atom_b, nullptr, nullptr, nullptr,
        out, 128);
    hmma_gemm<256, 128, 512><<<GC, 512, SMEM_128>>>(
        2, NCL, p_pre_cl, p_S_cl, p_scale_cl, p_shift_cl,
        p_Bt_hi + OFF_MC, p_Bt_lo + OFF_MC, merge_cl_b, nullptr, nullptr, nullptr,
        out + (size_t)NATOM * HD, 128);
}

// round 9
// speedup vs baseline: 1.0790x; 1.0790x over previous
#include <cuda_runtime.h>
#include <cuda_bf16.h>
#include <cstdint>
#include <cstddef>

#define NATOM 100000
#define NCL   25000
#define EA    600000
#define EC    100000
#define EB    100000
#define HD    128
#define PD    256
#define BN_EPS 1e-5f

// ---------------- scratch (static device memory; no allocs allowed) ----------------
__device__ float g_agg_atom[(size_t)NATOM * HD];
__device__ float g_agg_cl[(size_t)NCL * HD];
__device__ float g_aggm_c2a[(size_t)NATOM * HD];
__device__ float g_cnt_c2a[NATOM];
__device__ float g_aggm_a2c[(size_t)NCL * HD];
__device__ float g_cnt_a2c[NCL];
__device__ float g_pre_atom[(size_t)NATOM * PD];
__device__ float g_pre_cl[(size_t)NCL * PD];
__device__ float g_stats_atom[2 * PD];
__device__ float g_stats_cl[2 * PD];
__device__ float g_scale_atom[PD];
__device__ float g_shift_atom[PD];
__device__ float g_scale_cl[PD];
__device__ float g_shift_cl[PD];

// transposed + hi/lo-split weights, bf16:  [n][k] row-major per matrix
#define OFF_GA 0
#define OFF_GC 32768
#define OFF_SA 65536
#define OFF_SC 131072
#define OFF_MA 196608
#define OFF_MC 229376
__device__ __nv_bfloat16 g_Bt_hi[262144];
__device__ __nv_bfloat16 g_Bt_lo[262144];

// ---------------- helpers ---------------------------------------------------------
__device__ __forceinline__ uint32_t smem_u32(const void* p) {
    uint32_t a;
    asm("{ .reg .u64 t; cvta.to.shared.u64 t, %1; cvt.u32.u64 %0, t; }" : "=r"(a) : "l"(p));
    return a;
}
__device__ __forceinline__ void ldm_x4(uint32_t* r, uint32_t addr) {
    asm volatile("ldmatrix.sync.aligned.m8n8.x4.shared.b16 {%0,%1,%2,%3}, [%4];"
                 : "=r"(r[0]), "=r"(r[1]), "=r"(r[2]), "=r"(r[3]) : "r"(addr));
}
__device__ __forceinline__ void mma16816(float* c, const uint32_t* a, const uint32_t* b) {
    asm volatile("mma.sync.aligned.m16n8k16.row.col.f32.bf16.bf16.f32 "
                 "{%0,%1,%2,%3}, {%4,%5,%6,%7}, {%8,%9}, {%0,%1,%2,%3};"
                 : "+f"(c[0]), "+f"(c[1]), "+f"(c[2]), "+f"(c[3])
                 : "r"(a[0]), "r"(a[1]), "r"(a[2]), "r"(a[3]), "r"(b[0]), "r"(b[1]));
}
__device__ __forceinline__ void red_v4(float* p, float a, float b, float c, float d) {
    asm volatile("red.global.add.v4.f32 [%0], {%1,%2,%3,%4};"
                 :: "l"(p), "f"(a), "f"(b), "f"(c), "f"(d) : "memory");
}
__device__ __forceinline__ void cp16(uint32_t s, const void* g) {
    asm volatile("cp.async.cg.shared.global [%0], [%1], 16;" :: "r"(s), "l"(g));
}
__device__ __forceinline__ uint32_t pack_lo_bf16(float lox, float loy) {
    uint32_t r;
    asm("cvt.rn.bf16x2.f32 %0, %1, %2;" : "=r"(r) : "f"(loy), "f"(lox));
    return r;
}

// ---------------- edge scatter kernels --------------------------------------------
// gine: 1 edge per warp (round-7 proven); sage: 2 edges per warp (measured faster)
__global__ void gine_scatter(const float* __restrict__ x, const float* __restrict__ ea,
                             const int* __restrict__ ei, int E, float* __restrict__ agg) {
    int warp = (blockIdx.x * blockDim.x + threadIdx.x) >> 5;
    int lane = threadIdx.x & 31;
    if (warp >= E) return;
    int src = ei[warp];
    int dst = ei[E + warp];
    float4 xv = reinterpret_cast<const float4*>(x + (size_t)src * HD)[lane];
    float4 ev = reinterpret_cast<const float4*>(ea + (size_t)warp * HD)[lane];
    red_v4(agg + (size_t)dst * HD + lane * 4,
           fmaxf(xv.x + ev.x, 0.0f), fmaxf(xv.y + ev.y, 0.0f),
           fmaxf(xv.z + ev.z, 0.0f), fmaxf(xv.w + ev.w, 0.0f));
}

__global__ void sage_scatter(const float* __restrict__ xsrc, const int* __restrict__ ei,
                             int E, float* __restrict__ aggm, float* __restrict__ cnt) {
    int warp = (blockIdx.x * blockDim.x + threadIdx.x) >> 5;
    int lane = threadIdx.x & 31;
    int e0 = warp * 2;
    if (e0 >= E) return;
    int e1 = e0 + 1;
    int src0 = ei[e0], src1 = ei[e1];
    int dst0 = ei[E + e0], dst1 = ei[E + e1];
    float4 xv0 = reinterpret_cast<const float4*>(xsrc + (size_t)src0 * HD)[lane];
    float4 xv1 = reinterpret_cast<const float4*>(xsrc + (size_t)src1 * HD)[lane];
    red_v4(aggm + (size_t)dst0 * HD + lane * 4, xv0.x, xv0.y, xv0.z, xv0.w);
    red_v4(aggm + (size_t)dst1 * HD + lane * 4, xv1.x, xv1.y, xv1.z, xv1.w);
    if (lane == 0) {
        atomicAdd(&cnt[dst0], 1.0f);
        atomicAdd(&cnt[dst1], 1.0f);
    }
}

// ---------------- BN finalize (both sets, one launch) -----------------------------
__global__ void bn_finalize2(const float* __restrict__ sa, const float* __restrict__ sc,
                             const float* __restrict__ ga, const float* __restrict__ ba,
                             const float* __restrict__ gc, const float* __restrict__ bc,
                             float* __restrict__ scaleA, float* __restrict__ shiftA,
                             float* __restrict__ scaleC, float* __restrict__ shiftC) {
    int c = threadIdx.x & 255;
    if (threadIdx.x < 256) {
        float invM = 1.0f / NATOM;
        float mu = sa[c] * invM;
        float var = sa[PD + c] * invM - mu * mu;
        float s = ga[c] * rsqrtf(var + BN_EPS);
        scaleA[c] = s;
        shiftA[c] = ba[c] - mu * s;
    } else {
        float invM = 1.0f / NCL;
        float mu = sc[c] * invM;
        float var = sc[PD + c] * invM - mu * mu;
        float s = gc[c] * rsqrtf(var + BN_EPS);
        scaleC[c] = s;
        shiftC[c] = bc[c] - mu * s;
    }
}

// ---------------- fused weight transpose + hi/lo split (one launch) ---------------
struct WsplitArgs { const float* src[8]; };
__constant__ int c_ws_N[8]     = {256, 256, 256, 256, 256, 256, 128, 128};
__constant__ int c_ws_koff[8]  = {0, 0, 0, 128, 0, 128, 0, 0};
__constant__ int c_ws_kout[8]  = {128, 128, 256, 256, 256, 256, 256, 256};
__constant__ int c_ws_doff[8]  = {OFF_GA, OFF_GC, OFF_SA, OFF_SA, OFF_SC, OFF_SC, OFF_MA, OFF_MC};

__global__ void wsplit_all(WsplitArgs args,
                           __nv_bfloat16* __restrict__ oh, __nv_bfloat16* __restrict__ ol) {
    int i = blockIdx.x * blockDim.x + threadIdx.x;   // 0 .. 262143
    int seg = i >> 15;
    int w = i & 32767;
    int N = c_ws_N[seg];
    int k = w / N, n = w - k * N;
    float v = args.src[seg][w];
    uint32_t bits = __float_as_uint(v);
    uint32_t hbits = bits & 0xFFFF0000u;
    float lo = v - __uint_as_float(hbits);
    size_t o = (size_t)n * c_ws_kout[seg] + c_ws_koff[seg] + k + c_ws_doff[seg];
    oh[o] = __ushort_as_bfloat16((unsigned short)(hbits >> 16));
    ol[o] = __float2bfloat16(lo);
}

// ---------------- GINE GEMM (mode 0 of the proven template, + fused stats) --------
#define SMO_AH   1024
#define SMO_AL   33792
#define SMO_BH   66560

__global__ __launch_bounds__(512)
void gine_gemm(int M,
               const float* __restrict__ A0, const float* __restrict__ A1,
               const __nv_bfloat16* __restrict__ Bt_hi,
               const __nv_bfloat16* __restrict__ Bt_lo,
               const float* __restrict__ bias0,
               const float* __restrict__ epsPtr, float* __restrict__ statsG,
               float* __restrict__ C) {
    constexpr int SMO_BL = SMO_BH + 256 * 256;
    extern __shared__ char smem[];
    uint32_t sb = smem_u32(smem);
    const int tid = threadIdx.x;
    const int wid = tid >> 5;
    const int lid = tid & 31;
    const int wm = wid & 3;
    const int wn = wid >> 2;
    const int m0 = blockIdx.x * 128;

    float* bias_s = reinterpret_cast<float*>(smem);
    if (tid < 256) bias_s[tid] = bias0[tid];

    const float ef = 1.0f + *epsPtr;

    float acc[2][8][4];
#pragma unroll
    for (int mt = 0; mt < 2; mt++)
#pragma unroll
        for (int nt = 0; nt < 8; nt++)
#pragma unroll
            for (int j = 0; j < 4; j++) acc[mt][nt][j] = 0.0f;

    // B tile via cp.async (single 128-k chunk)
#pragma unroll
    for (int it = 0; it < 8; it++) {
        int idx = tid + it * 512;
        int n = idx >> 4;
        int ch = idx & 15;
        uint32_t off = n * 256 + ((ch ^ (n & 7)) << 4);
        cp16(sb + SMO_BH + off, Bt_hi + (size_t)n * 128 + ch * 8);
        cp16(sb + SMO_BL + off, Bt_lo + (size_t)n * 128 + ch * 8);
    }
    asm volatile("cp.async.commit_group;" ::: "memory");

    // A tile: transform + truncation split
#pragma unroll
    for (int it = 0; it < 8; it++) {
        int idx = tid + it * 512;
        int r = idx >> 5;
        int c4 = (idx & 31) * 4;
        int gr = m0 + r;
        float4 v = make_float4(0.f, 0.f, 0.f, 0.f);
        if (gr < M) {
            float4 a = *reinterpret_cast<const float4*>(A0 + (size_t)gr * 128 + c4);
            float4 g = *reinterpret_cast<const float4*>(A1 + (size_t)gr * 128 + c4);
            v.x = fmaf(ef, a.x, g.x); v.y = fmaf(ef, a.y, g.y);
            v.z = fmaf(ef, a.z, g.z); v.w = fmaf(ef, a.w, g.w);
        }
        uint32_t bx = __float_as_uint(v.x), by = __float_as_uint(v.y);
        uint32_t bz = __float_as_uint(v.z), bw = __float_as_uint(v.w);
        uint2 hp, lp;
        hp.x = __byte_perm(bx, by, 0x7632);
        hp.y = __byte_perm(bz, bw, 0x7632);
        lp.x = pack_lo_bf16(v.x - __uint_as_float(bx & 0xFFFF0000u),
                            v.y - __uint_as_float(by & 0xFFFF0000u));
        lp.y = pack_lo_bf16(v.z - __uint_as_float(bz & 0xFFFF0000u),
                            v.w - __uint_as_float(bw & 0xFFFF0000u));
        uint32_t off = r * 256 + (((c4 >> 3) ^ (r & 7)) << 4) + ((c4 & 4) << 1);
        *reinterpret_cast<uint2*>(smem + SMO_AH + off) = hp;
        *reinterpret_cast<uint2*>(smem + SMO_AL + off) = lp;
    }
    asm volatile("cp.async.wait_group 0;" ::: "memory");
    __syncthreads();

    const int arow = wm * 32 + (lid & 15);
    const int akp = lid >> 4;
    const int bn = wn * 64 + (lid & 7) + ((lid >> 4) << 3);
    const int bkp = (lid >> 3) & 1;
#pragma unroll
    for (int ks = 0; ks < 8; ks++) {
        uint32_t ah[2][4], al[2][4];
#pragma unroll
        for (int mt = 0; mt < 2; mt++) {
            int r = arow + mt * 16;
            uint32_t ch = (uint32_t)((ks * 2 + akp) ^ (r & 7));
            uint32_t off = r * 256 + (ch << 4);
            ldm_x4(ah[mt], sb + SMO_AH + off);
            ldm_x4(al[mt], sb + SMO_AL + off);
        }
#pragma unroll
        for (int np = 0; np < 4; np++) {
            int n = bn + np * 16;
            uint32_t ch = (uint32_t)((ks * 2 + bkp) ^ (n & 7));
            uint32_t off = n * 256 + (ch << 4);
            uint32_t bh[4], bl[4];
            ldm_x4(bh, sb + SMO_BH + off);
            ldm_x4(bl, sb + SMO_BL + off);
#pragma unroll
            for (int mt = 0; mt < 2; mt++) {
#pragma unroll
                for (int sn = 0; sn < 2; sn++) {
                    float* c = acc[mt][np * 2 + sn];
                    mma16816(c, ah[mt], bh + sn * 2);
                    mma16816(c, ah[mt], bl + sn * 2);
                    mma16816(c, al[mt], bh + sn * 2);
                }
            }
        }
    }

    // epilogue + fused column stats
    const int g = lid >> 2;
    const int tig = lid & 3;
#pragma unroll
    for (int nt = 0; nt < 8; nt++) {
        int nl = wn * 64 + nt * 8 + 2 * tig;
        float b0 = bias_s[nl], b1 = bias_s[nl + 1];
        float s0 = 0.f, s1 = 0.f, q0 = 0.f, q1 = 0.f;
#pragma unroll
        for (int mt = 0; mt < 2; mt++) {
            int m = m0 + wm * 32 + mt * 16 + g;
            if (m < M) {
                float ox = acc[mt][nt][0] + b0, oy = acc[mt][nt][1] + b1;
                *reinterpret_cast<float2*>(C + (size_t)m * PD + nl) = make_float2(ox, oy);
                s0 += ox; s1 += oy; q0 += ox * ox; q1 += oy * oy;
            }
            if (m + 8 < M) {
                float ox = acc[mt][nt][2] + b0, oy = acc[mt][nt][3] + b1;
                *reinterpret_cast<float2*>(C + (size_t)(m + 8) * PD + nl) = make_float2(ox, oy);
                s0 += ox; s1 += oy; q0 += ox * ox; q1 += oy * oy;
            }
        }
#pragma unroll
        for (int d = 4; d < 32; d <<= 1) {
            s0 += __shfl_xor_sync(0xFFFFFFFFu, s0, d);
            s1 += __shfl_xor_sync(0xFFFFFFFFu, s1, d);
            q0 += __shfl_xor_sync(0xFFFFFFFFu, q0, d);
            q1 += __shfl_xor_sync(0xFFFFFFFFu, q1, d);
        }
        if (g == 0) {
            atomicAdd(statsG + nl, s0);
            atomicAdd(statsG + nl + 1, s1);
            atomicAdd(statsG + PD + nl, q0);
            atomicAdd(statsG + PD + nl + 1, q1);
        }
    }
}

// ---------------- fused SAGE + MERGE kernel ----------------------------------------
// Phase 1: S = [aggm/cnt | xdst] @ [Wl;Wr] + (bl+br)        (K=256, N=256)
// Phase 2: A2 = relu(pre*scale+shift) + S  -> smem (split bf16)
// Phase 3: out = A2 @ mergeW + mbias                        (K=256, N=128)
#define F_BIAS1 0
#define F_BIAS2 1024
#define F_SCALE 1536
#define F_SHIFT 2560
#define F_A1H   4096
#define F_A1L   36864
#define F_B1H   69632
#define F_B1L   135168
#define F_A2H   F_B1H
#define F_A2L   F_B1L
#define F_B2H   F_A1H
#define F_B2L   F_A1L
#define SMEM_FUSED 200704

__global__ __launch_bounds__(512)
void sage_merge_fused(int M,
                      const float* __restrict__ aggm, const float* __restrict__ xdst,
                      const float* __restrict__ cnt,
                      const __nv_bfloat16* __restrict__ B1h, const __nv_bfloat16* __restrict__ B1l,
                      const float* __restrict__ bl, const float* __restrict__ br,
                      const float* __restrict__ pre,
                      const float* __restrict__ scale, const float* __restrict__ shift,
                      const __nv_bfloat16* __restrict__ B2h, const __nv_bfloat16* __restrict__ B2l,
                      const float* __restrict__ mbias, float* __restrict__ Cout) {
    extern __shared__ char smem[];
    uint32_t sb = smem_u32(smem);
    const int tid = threadIdx.x;
    const int wid = tid >> 5;
    const int lid = tid & 31;
    const int m0 = blockIdx.x * 128;

    float* bias1_s = reinterpret_cast<float*>(smem + F_BIAS1);
    float* bias2_s = reinterpret_cast<float*>(smem + F_BIAS2);
    float* scale_s = reinterpret_cast<float*>(smem + F_SCALE);
    float* shift_s = reinterpret_cast<float*>(smem + F_SHIFT);
    if (tid < 256) {
        bias1_s[tid] = bl[tid] + br[tid];
        scale_s[tid] = scale[tid];
        shift_s[tid] = shift[tid];
    } else if (tid < 384) {
        bias2_s[tid - 256] = mbias[tid - 256];
    }

    // ===== Phase 1: SAGE GEMM, warps 4m x 4n =====
    const int wm = wid & 3;
    const int wn = wid >> 2;
    float acc[2][8][4];
#pragma unroll
    for (int mt = 0; mt < 2; mt++)
#pragma unroll
        for (int nt = 0; nt < 8; nt++)
#pragma unroll
            for (int j = 0; j < 4; j++) acc[mt][nt][j] = 0.0f;

    for (int kk = 0; kk < 256; kk += 128) {
        // B1 tile via cp.async: 256 n-rows x 128 k
#pragma unroll
        for (int it = 0; it < 8; it++) {
            int idx = tid + it * 512;
            int n = idx >> 4;
            int ch = idx & 15;
            uint32_t off = n * 256 + ((ch ^ (n & 7)) << 4);
            cp16(sb + F_B1H + off, B1h + (size_t)n * 256 + kk + ch * 8);
            cp16(sb + F_B1L + off, B1l + (size_t)n * 256 + kk + ch * 8);
        }
        asm volatile("cp.async.commit_group;" ::: "memory");

        // A1 tile: [aggm/cnt | xdst], truncation split
#pragma unroll
        for (int it = 0; it < 8; it++) {
            int idx = tid + it * 512;
            int r = idx >> 5;
            int c4 = (idx & 31) * 4;
            int gr = m0 + r;
            int gk = kk + c4;
            float4 v = make_float4(0.f, 0.f, 0.f, 0.f);
            if (gr < M) {
                if (gk < 128) {
                    float4 a = *reinterpret_cast<const float4*>(aggm + (size_t)gr * 128 + gk);
                    float inv = __frcp_rn(fmaxf(cnt[gr], 1.0f));
                    v.x = a.x * inv; v.y = a.y * inv; v.z = a.z * inv; v.w = a.w * inv;
                } else {
                    v = *reinterpret_cast<const float4*>(xdst + (size_t)gr * 128 + (gk - 128));
                }
            }
            uint32_t bx = __float_as_uint(v.x), by = __float_as_uint(v.y);
            uint32_t bz = __float_as_uint(v.z), bw = __float_as_uint(v.w);
            uint2 hp, lp;
            hp.x = __byte_perm(bx, by, 0x7632);
            hp.y = __byte_perm(bz, bw, 0x7632);
            lp.x = pack_lo_bf16(v.x - __uint_as_float(bx & 0xFFFF0000u),
                                v.y - __uint_as_float(by & 0xFFFF0000u));
            lp.y = pack_lo_bf16(v.z - __uint_as_float(bz & 0xFFFF0000u),
                                v.w - __uint_as_float(bw & 0xFFFF0000u));
            uint32_t off = r * 256 + (((c4 >> 3) ^ (r & 7)) << 4) + ((c4 & 4) << 1);
            *reinterpret_cast<uint2*>(smem + F_A1H + off) = hp;
            *reinterpret_cast<uint2*>(smem + F_A1L + off) = lp;
        }
        asm volatile("cp.async.wait_group 0;" ::: "memory");
        __syncthreads();

        const int arow = wm * 32 + (lid & 15);
        const int akp = lid >> 4;
        const int bn = wn * 64 + (lid & 7) + ((lid >> 4) << 3);
        const int bkp = (lid >> 3) & 1;
#pragma unroll
        for (int ks = 0; ks < 8; ks++) {
            uint32_t ah[2][4], al[2][4];
#pragma unroll
            for (int mt = 0; mt < 2; mt++) {
                int r = arow + mt * 16;
                uint32_t ch = (uint32_t)((ks * 2 + akp) ^ (r & 7));
                uint32_t off = r * 256 + (ch << 4);
                ldm_x4(ah[mt], sb + F_A1H + off);
                ldm_x4(al[mt], sb + F_A1L + off);
            }
#pragma unroll
            for (int np = 0; np < 4; np++) {
                int n = bn + np * 16;
                uint32_t ch = (uint32_t)((ks * 2 + bkp) ^ (n & 7));
                uint32_t off = n * 256 + (ch << 4);
                uint32_t bh[4], blx[4];
                ldm_x4(bh, sb + F_B1H + off);
                ldm_x4(blx, sb + F_B1L + off);
#pragma unroll
                for (int mt = 0; mt < 2; mt++) {
#pragma unroll
                    for (int sn = 0; sn < 2; sn++) {
                        float* c = acc[mt][np * 2 + sn];
                        mma16816(c, ah[mt], bh + sn * 2);
                        mma16816(c, ah[mt], blx + sn * 2);
                        mma16816(c, al[mt], bh + sn * 2);
                    }
                }
            }
        }
        __syncthreads();
    }

    // ===== Phase 2: A2 = relu(pre*scale+shift) + S  -> smem split bf16 =====
    {
        const int g = lid >> 2;
        const int tig = lid & 3;
#pragma unroll
        for (int nt = 0; nt < 8; nt++) {
            int nl = wn * 64 + nt * 8 + 2 * tig;
            float b0 = bias1_s[nl], b1 = bias1_s[nl + 1];
            float sc0 = scale_s[nl], sc1 = scale_s[nl + 1];
            float sh0 = shift_s[nl], sh1 = shift_s[nl + 1];
#pragma unroll
            for (int mt = 0; mt < 2; mt++) {
#pragma unroll
                for (int half = 0; half < 2; half++) {
                    int r = wm * 32 + mt * 16 + g + half * 8;
                    int m = m0 + r;
                    float ax = 0.f, ay = 0.f;
                    if (m < M) {
                        float2 p = *reinterpret_cast<const float2*>(pre + (size_t)m * PD + nl);
                        ax = fmaxf(fmaf(p.x, sc0, sh0), 0.f) + acc[mt][nt][half * 2 + 0] + b0;
                        ay = fmaxf(fmaf(p.y, sc1, sh1), 0.f) + acc[mt][nt][half * 2 + 1] + b1;
                    }
                    uint32_t bx = __float_as_uint(ax), by = __float_as_uint(ay);
                    uint32_t hp = __byte_perm(bx, by, 0x7632);
                    uint32_t lp = pack_lo_bf16(ax - __uint_as_float(bx & 0xFFFF0000u),
                                               ay - __uint_as_float(by & 0xFFFF0000u));
                    uint32_t off = r * 512 + (((nl >> 3) ^ (r & 7)) << 4) + (nl & 7) * 2;
                    *reinterpret_cast<uint32_t*>(smem + F_A2H + off) = hp;
                    *reinterpret_cast<uint32_t*>(smem + F_A2L + off) = lp;
                }
            }
        }
    }
    __syncthreads();

    // ===== Phase 3: merge GEMM from smem A2, warps 8m x 2n =====
    const int wm2 = wid & 7;
    const int wn2 = wid >> 3;
    float acc2[8][4];
#pragma unroll
    for (int nt = 0; nt < 8; nt++)
#pragma unroll
        for (int j = 0; j < 4; j++) acc2[nt][j] = 0.0f;

    const int arow2 = wm2 * 16 + (lid & 15);
    const int akp2 = lid >> 4;
    const int bn2 = wn2 * 64 + (lid & 7) + ((lid >> 4) << 3);
    const int bkp2 = (lid >> 3) & 1;

    for (int kk = 0; kk < 256; kk += 128) {
        // B2 tile via cp.async: 128 n-rows x 128 k
#pragma unroll
        for (int it = 0; it < 4; it++) {
            int idx = tid + it * 512;
            int n = idx >> 4;
            int ch = idx & 15;
            uint32_t off = n * 256 + ((ch ^ (n & 7)) << 4);
            cp16(sb + F_B2H + off, B2h + (size_t)n * 256 + kk + ch * 8);
            cp16(sb + F_B2L + off, B2l + (size_t)n * 256 + kk + ch * 8);
        }
        asm volatile("cp.async.commit_group;" ::: "memory");
        asm volatile("cp.async.wait_group 0;" ::: "memory");
        __syncthreads();

#pragma unroll
        for (int ks = 0; ks < 8; ks++) {
            uint32_t ah[4], al[4];
            {
                int r = arow2;
                uint32_t ch = (uint32_t)(((kk >> 3) + ks * 2 + akp2) ^ (r & 7));
                uint32_t off = r * 512 + (ch << 4);
                ldm_x4(ah, sb + F_A2H + off);
                ldm_x4(al, sb + F_A2L + off);
            }
#pragma unroll
            for (int np = 0; np < 4; np++) {
                int n = bn2 + np * 16;
                uint32_t ch = (uint32_t)((ks * 2 + bkp2) ^ (n & 7));
                uint32_t off = n * 256 + (ch << 4);
                uint32_t bh[4], blx[4];
                ldm_x4(bh, sb + F_B2H + off);
                ldm_x4(blx, sb + F_B2L + off);
#pragma unroll
                for (int sn = 0; sn < 2; sn++) {
                    float* c = acc2[np * 2 + sn];
                    mma16816(c, ah, bh + sn * 2);
                    mma16816(c, ah, blx + sn * 2);
                    mma16816(c, al, bh + sn * 2);
                }
            }
        }
        __syncthreads();
    }

    // epilogue: out = acc2 + mbias
    {
        const int g = lid >> 2;
        const int tig = lid & 3;
#pragma unroll
        for (int nt = 0; nt < 8; nt++) {
            int nl = wn2 * 64 + nt * 8 + 2 * tig;
            float b0 = bias2_s[nl], b1 = bias2_s[nl + 1];
            int m = m0 + wm2 * 16 + g;
            if (m < M) {
                *reinterpret_cast<float2*>(Cout + (size_t)m * HD + nl) =
                    make_float2(acc2[nt][0] + b0, acc2[nt][1] + b1);
            }
            if (m + 8 < M) {
                *reinterpret_cast<float2*>(Cout + (size_t)(m + 8) * HD + nl) =
                    make_float2(acc2[nt][2] + b0, acc2[nt][3] + b1);
            }
        }
    }
}

// -----------------------------------------------------------------------------------
extern "C" void kernel_launch(void* const* d_in, const int* in_sizes, int n_in,
                              void* d_out, int out_size) {
    const float* x         = (const float*)d_in[0];
    const float* edge_attr = (const float*)d_in[1];
    const float* x_cl      = (const float*)d_in[2];
    const float* c2c_ea    = (const float*)d_in[3];

    int pbase, ebase;
    if (in_sizes[4] == 2 * EA) { ebase = 4; pbase = 8; }
    else                       { pbase = 4; ebase = 26; }

    const int* ei_a   = (const int*)d_in[ebase + 0];
    const int* ei_c2c = (const int*)d_in[ebase + 1];
    const int* ei_a2c = (const int*)d_in[ebase + 2];
    const int* ei_c2a = (const int*)d_in[ebase + 3];

    const float* atom_eps   = (const float*)d_in[pbase + 0];
    const float* atom_W     = (const float*)d_in[pbase + 1];
    const float* atom_b     = (const float*)d_in[pbase + 2];
    const float* atom_gamma = (const float*)d_in[pbase + 3];
    const float* atom_beta  = (const float*)d_in[pbase + 4];
    const float* cl_eps     = (const float*)d_in[pbase + 5];
    const float* cl_W       = (const float*)d_in[pbase + 6];
    const float* cl_b       = (const float*)d_in[pbase + 7];
    const float* cl_gamma   = (const float*)d_in[pbase + 8];
    const float* cl_beta    = (const float*)d_in[pbase + 9];
    const float* a2c_Wl     = (const float*)d_in[pbase + 10];
    const float* a2c_bl     = (const float*)d_in[pbase + 11];
    const float* a2c_Wr     = (const float*)d_in[pbase + 12];
    const float* a2c_br     = (const float*)d_in[pbase + 13];
    const float* c2a_Wl     = (const float*)d_in[pbase + 14];
    const float* c2a_bl     = (const float*)d_in[pbase + 15];
    const float* c2a_Wr     = (const float*)d_in[pbase + 16];
    const float* c2a_br     = (const float*)d_in[pbase + 17];
    const float* merge_atom_W = (const float*)d_in[pbase + 18];
    const float* merge_atom_b = (const float*)d_in[pbase + 19];
    const float* merge_cl_W   = (const float*)d_in[pbase + 20];
    const float* merge_cl_b   = (const float*)d_in[pbase + 21];

    float* out = (float*)d_out;

    float *p_agg_atom, *p_agg_cl, *p_aggm_c2a, *p_cnt_c2a, *p_aggm_a2c, *p_cnt_a2c;
    float *p_pre_atom, *p_pre_cl;
    float *p_stats_atom, *p_stats_cl, *p_scale_atom, *p_shift_atom, *p_scale_cl, *p_shift_cl;
    __nv_bfloat16 *p_Bt_hi, *p_Bt_lo;
    cudaGetSymbolAddress((void**)&p_agg_atom, g_agg_atom);
    cudaGetSymbolAddress((void**)&p_agg_cl, g_agg_cl);
    cudaGetSymbolAddress((void**)&p_aggm_c2a, g_aggm_c2a);
    cudaGetSymbolAddress((void**)&p_cnt_c2a, g_cnt_c2a);
    cudaGetSymbolAddress((void**)&p_aggm_a2c, g_aggm_a2c);
    cudaGetSymbolAddress((void**)&p_cnt_a2c, g_cnt_a2c);
    cudaGetSymbolAddress((void**)&p_pre_atom, g_pre_atom);
    cudaGetSymbolAddress((void**)&p_pre_cl, g_pre_cl);
    cudaGetSymbolAddress((void**)&p_stats_atom, g_stats_atom);
    cudaGetSymbolAddress((void**)&p_stats_cl, g_stats_cl);
    cudaGetSymbolAddress((void**)&p_scale_atom, g_scale_atom);
    cudaGetSymbolAddress((void**)&p_shift_atom, g_shift_atom);
    cudaGetSymbolAddress((void**)&p_scale_cl, g_scale_cl);
    cudaGetSymbolAddress((void**)&p_shift_cl, g_shift_cl);
    cudaGetSymbolAddress((void**)&p_Bt_hi, g_Bt_hi);
    cudaGetSymbolAddress((void**)&p_Bt_lo, g_Bt_lo);

    cudaMemsetAsync(p_agg_atom, 0, (size_t)NATOM * HD * 4, 0);
    cudaMemsetAsync(p_agg_cl, 0, (size_t)NCL * HD * 4, 0);
    cudaMemsetAsync(p_aggm_c2a, 0, (size_t)NATOM * HD * 4, 0);
    cudaMemsetAsync(p_cnt_c2a, 0, (size_t)NATOM * 4, 0);
    cudaMemsetAsync(p_aggm_a2c, 0, (size_t)NCL * HD * 4, 0);
    cudaMemsetAsync(p_cnt_a2c, 0, (size_t)NCL * 4, 0);
    cudaMemsetAsync(p_stats_atom, 0, 2 * PD * 4, 0);
    cudaMemsetAsync(p_stats_cl, 0, 2 * PD * 4, 0);

    const int SMEM_GINE = 66560 + 256 * 256 * 2;  // 197632
    cudaFuncSetAttribute((const void*)gine_gemm,
                         cudaFuncAttributeMaxDynamicSharedMemorySize, SMEM_GINE);
    cudaFuncSetAttribute((const void*)sage_merge_fused,
                         cudaFuncAttributeMaxDynamicSharedMemorySize, SMEM_FUSED);

    // ---- fused weight transpose + split (one launch) ----
    {
        WsplitArgs wa;
        wa.src[0] = atom_W;  wa.src[1] = cl_W;
        wa.src[2] = c2a_Wl;  wa.src[3] = c2a_Wr;
        wa.src[4] = a2c_Wl;  wa.src[5] = a2c_Wr;
        wa.src[6] = merge_atom_W; wa.src[7] = merge_cl_W;
        wsplit_all<<<1024, 256>>>(wa, p_Bt_hi, p_Bt_lo);
    }

    // ---- scatter passes ----
    gine_scatter<<<(EA * 32 + 255) / 256, 256>>>(x, edge_attr, ei_a, EA, p_agg_atom);
    gine_scatter<<<(EC * 32 + 255) / 256, 256>>>(x_cl, c2c_ea, ei_c2c, EC, p_agg_cl);
    sage_scatter<<<(EB / 2 * 32 + 255) / 256, 256>>>(x, ei_a2c, EB, p_aggm_a2c, p_cnt_a2c);
    sage_scatter<<<(EB / 2 * 32 + 255) / 256, 256>>>(x_cl, ei_c2a, EB, p_aggm_c2a, p_cnt_c2a);

    const int GA = (NATOM + 127) / 128;  // 782
    const int GC = (NCL + 127) / 128;    // 196

    // ---- GINE GEMMs (pre-BN, fused column stats) ----
    gine_gemm<<<GA, 512, SMEM_GINE>>>(NATOM, x, p_agg_atom,
        p_Bt_hi + OFF_GA, p_Bt_lo + OFF_GA, atom_b, atom_eps, p_stats_atom, p_pre_atom);
    gine_gemm<<<GC, 512, SMEM_GINE>>>(NCL, x_cl, p_agg_cl,
        p_Bt_hi + OFF_GC, p_Bt_lo + OFF_GC, cl_b, cl_eps, p_stats_cl, p_pre_cl);

    bn_finalize2<<<1, 512>>>(p_stats_atom, p_stats_cl, atom_gamma, atom_beta,
                             cl_gamma, cl_beta, p_scale_atom, p_shift_atom,
                             p_scale_cl, p_shift_cl);

    // ---- fused SAGE + MERGE ----
    sage_merge_fused<<<GA, 512, SMEM_FUSED>>>(NATOM,
        p_aggm_c2a, x, p_cnt_c2a,
        p_Bt_hi + OFF_SA, p_Bt_lo + OFF_SA, c2a_bl, c2a_br,
        p_pre_atom, p_scale_atom, p_shift_atom,
        p_Bt_hi + OFF_MA, p_Bt_lo + OFF_MA, merge_atom_b, out);
    sage_merge_fused<<<GC, 512, SMEM_FUSED>>>(NCL,
        p_aggm_a2c, x_cl, p_cnt_a2c,
        p_Bt_hi + OFF_SC, p_Bt_lo + OFF_SC, a2c_bl, a2c_br,
        p_pre_cl, p_scale_cl, p_shift_cl,
        p_Bt_hi + OFF_MC, p_Bt_lo + OFF_MC, merge_cl_b,
        out + (size_t)NATOM * HD);
}

// round 10
// speedup vs baseline: 1.2157x; 1.1267x over previous
#include <cuda_runtime.h>
#include <cuda_bf16.h>
#include <cstdint>
#include <cstddef>

#define NATOM 100000
#define NCL   25000
#define EA    600000
#define EC    100000
#define EB    100000
#define HD    128
#define PD    256
#define BN_EPS 1e-5f
#define GAC   782      // (NATOM+127)/128
#define GCC   196      // (NCL+127)/128

// ---------------- zeroed scratch arena (single memset) -----------------------------
#define Z_AGG_ATOM  0
#define Z_AGG_CL    12800000
#define Z_AGGM_C2A  16000000
#define Z_AGGM_A2C  28800000
#define Z_CNT_C2A   32000000
#define Z_CNT_A2C   32100000
#define Z_STATS_A   32125000
#define Z_STATS_C   32125512
#define Z_TOTAL     32126024
__device__ float g_zero[Z_TOTAL];

// non-zeroed scratch
__device__ float g_pre_atom[(size_t)NATOM * PD];
__device__ float g_pre_cl[(size_t)NCL * PD];
__device__ float g_scale_atom[PD];
__device__ float g_shift_atom[PD];
__device__ float g_scale_cl[PD];
__device__ float g_shift_cl[PD];

// transposed + hi/lo-split weights, bf16:  [n][k] row-major per matrix
#define OFF_GA 0
#define OFF_GC 32768
#define OFF_SA 65536
#define OFF_SC 131072
#define OFF_MA 196608
#define OFF_MC 229376
__device__ __nv_bfloat16 g_Bt_hi[262144];
__device__ __nv_bfloat16 g_Bt_lo[262144];

// ---------------- helpers ---------------------------------------------------------
__device__ __forceinline__ uint32_t smem_u32(const void* p) {
    uint32_t a;
    asm("{ .reg .u64 t; cvta.to.shared.u64 t, %1; cvt.u32.u64 %0, t; }" : "=r"(a) : "l"(p));
    return a;
}
__device__ __forceinline__ void ldm_x4(uint32_t* r, uint32_t addr) {
    asm volatile("ldmatrix.sync.aligned.m8n8.x4.shared.b16 {%0,%1,%2,%3}, [%4];"
                 : "=r"(r[0]), "=r"(r[1]), "=r"(r[2]), "=r"(r[3]) : "r"(addr));
}
__device__ __forceinline__ void mma16816(float* c, const uint32_t* a, const uint32_t* b) {
    asm volatile("mma.sync.aligned.m16n8k16.row.col.f32.bf16.bf16.f32 "
                 "{%0,%1,%2,%3}, {%4,%5,%6,%7}, {%8,%9}, {%0,%1,%2,%3};"
                 : "+f"(c[0]), "+f"(c[1]), "+f"(c[2]), "+f"(c[3])
                 : "r"(a[0]), "r"(a[1]), "r"(a[2]), "r"(a[3]), "r"(b[0]), "r"(b[1]));
}
__device__ __forceinline__ void red_v4(float* p, float a, float b, float c, float d) {
    asm volatile("red.global.add.v4.f32 [%0], {%1,%2,%3,%4};"
                 :: "l"(p), "f"(a), "f"(b), "f"(c), "f"(d) : "memory");
}
__device__ __forceinline__ void cp16(uint32_t s, const void* g) {
    asm volatile("cp.async.cg.shared.global [%0], [%1], 16;" :: "r"(s), "l"(g));
}
__device__ __forceinline__ uint32_t pack_lo_bf16(float lox, float loy) {
    uint32_t r;
    asm("cvt.rn.bf16x2.f32 %0, %1, %2;" : "=r"(r) : "f"(loy), "f"(lox));
    return r;
}

// ---------------- mega scatter + wsplit (one launch) -------------------------------
__constant__ int c_ws_N[8]     = {256, 256, 256, 256, 256, 256, 128, 128};
__constant__ int c_ws_koff[8]  = {0, 0, 0, 128, 0, 128, 0, 0};
__constant__ int c_ws_kout[8]  = {128, 128, 256, 256, 256, 256, 256, 256};
__constant__ int c_ws_doff[8]  = {OFF_GA, OFF_GC, OFF_SA, OFF_SA, OFF_SC, OFF_SC, OFF_MA, OFF_MC};

struct MegaArgs {
    const float *x, *ea, *xcl, *cea;
    const int *ei_a, *ei_c, *ei_a2c, *ei_c2a;
    float *agg_atom, *agg_cl, *aggm_a2c, *cnt_a2c, *aggm_c2a, *cnt_c2a;
    const float* wsrc[8];
    __nv_bfloat16 *oh, *ol;
};

#define SCATTER_BLOCKS 100000   // 800000 warps
#define WSPLIT_BLOCKS  1024

__global__ void mega_scatter(MegaArgs A) {
    int b = blockIdx.x;
    if (b >= SCATTER_BLOCKS) {
        // ---- weight transpose + hi/lo split ----
        int i = (b - SCATTER_BLOCKS) * 256 + threadIdx.x;   // 0..262143
        int seg = i >> 15;
        int w = i & 32767;
        int N = c_ws_N[seg];
        int k = w / N, n = w - k * N;
        float v = A.wsrc[seg][w];
        uint32_t bits = __float_as_uint(v);
        uint32_t hbits = bits & 0xFFFF0000u;
        float lo = v - __uint_as_float(hbits);
        size_t o = (size_t)n * c_ws_kout[seg] + c_ws_koff[seg] + k + c_ws_doff[seg];
        A.oh[o] = __ushort_as_bfloat16((unsigned short)(hbits >> 16));
        A.ol[o] = __float2bfloat16(lo);
        return;
    }
    int w = b * 8 + (threadIdx.x >> 5);
    int lane = threadIdx.x & 31;
    if (w < 600000) {
        // gine atom, 1 edge/warp
        int e = w;
        int src = A.ei_a[e];
        int dst = A.ei_a[EA + e];
        float4 xv = reinterpret_cast<const float4*>(A.x + (size_t)src * HD)[lane];
        float4 ev = reinterpret_cast<const float4*>(A.ea + (size_t)e * HD)[lane];
        red_v4(A.agg_atom + (size_t)dst * HD + lane * 4,
               fmaxf(xv.x + ev.x, 0.0f), fmaxf(xv.y + ev.y, 0.0f),
               fmaxf(xv.z + ev.z, 0.0f), fmaxf(xv.w + ev.w, 0.0f));
    } else if (w < 700000) {
        // gine cluster, 1 edge/warp
        int e = w - 600000;
        int src = A.ei_c[e];
        int dst = A.ei_c[EC + e];
        float4 xv = reinterpret_cast<const float4*>(A.xcl + (size_t)src * HD)[lane];
        float4 ev = reinterpret_cast<const float4*>(A.cea + (size_t)e * HD)[lane];
        red_v4(A.agg_cl + (size_t)dst * HD + lane * 4,
               fmaxf(xv.x + ev.x, 0.0f), fmaxf(xv.y + ev.y, 0.0f),
               fmaxf(xv.z + ev.z, 0.0f), fmaxf(xv.w + ev.w, 0.0f));
    } else if (w < 750000) {
        // sage atom2c: src rows from x, 2 edges/warp
        int e0 = (w - 700000) * 2, e1 = e0 + 1;
        int s0 = A.ei_a2c[e0], s1 = A.ei_a2c[e1];
        int d0 = A.ei_a2c[EB + e0], d1 = A.ei_a2c[EB + e1];
        float4 v0 = reinterpret_cast<const float4*>(A.x + (size_t)s0 * HD)[lane];
        float4 v1 = reinterpret_cast<const float4*>(A.x + (size_t)s1 * HD)[lane];
        red_v4(A.aggm_a2c + (size_t)d0 * HD + lane * 4, v0.x, v0.y, v0.z, v0.w);
        red_v4(A.aggm_a2c + (size_t)d1 * HD + lane * 4, v1.x, v1.y, v1.z, v1.w);
        if (lane == 0) {
            atomicAdd(&A.cnt_a2c[d0], 1.0f);
            atomicAdd(&A.cnt_a2c[d1], 1.0f);
        }
    } else {
        // sage c2atom: src rows from x_cl, 2 edges/warp
        int e0 = (w - 750000) * 2, e1 = e0 + 1;
        int s0 = A.ei_c2a[e0], s1 = A.ei_c2a[e1];
        int d0 = A.ei_c2a[EB + e0], d1 = A.ei_c2a[EB + e1];
        float4 v0 = reinterpret_cast<const float4*>(A.xcl + (size_t)s0 * HD)[lane];
        float4 v1 = reinterpret_cast<const float4*>(A.xcl + (size_t)s1 * HD)[lane];
        red_v4(A.aggm_c2a + (size_t)d0 * HD + lane * 4, v0.x, v0.y, v0.z, v0.w);
        red_v4(A.aggm_c2a + (size_t)d1 * HD + lane * 4, v1.x, v1.y, v1.z, v1.w);
        if (lane == 0) {
            atomicAdd(&A.cnt_c2a[d0], 1.0f);
            atomicAdd(&A.cnt_c2a[d1], 1.0f);
        }
    }
}

// ---------------- BN finalize (both sets, one launch) -----------------------------
__global__ void bn_finalize2(const float* __restrict__ sa, const float* __restrict__ sc,
                             const float* __restrict__ ga, const float* __restrict__ ba,
                             const float* __restrict__ gc, const float* __restrict__ bc,
                             float* __restrict__ scaleA, float* __restrict__ shiftA,
                             float* __restrict__ scaleC, float* __restrict__ shiftC) {
    int c = threadIdx.x & 255;
    if (threadIdx.x < 256) {
        float invM = 1.0f / NATOM;
        float mu = sa[c] * invM;
        float var = sa[PD + c] * invM - mu * mu;
        float s = ga[c] * rsqrtf(var + BN_EPS);
        scaleA[c] = s;
        shiftA[c] = ba[c] - mu * s;
    } else {
        float invM = 1.0f / NCL;
        float mu = sc[c] * invM;
        float var = sc[PD + c] * invM - mu * mu;
        float s = gc[c] * rsqrtf(var + BN_EPS);
        scaleC[c] = s;
        shiftC[c] = bc[c] - mu * s;
    }
}

// ---------------- GINE GEMM pair (atom + cluster in one grid) ----------------------
#define SMO_AH   1024
#define SMO_AL   33792
#define SMO_BH   66560
#define SMEM_GINE (66560 + 256 * 256 * 2)

struct GineP {
    const float *A0, *A1;
    const __nv_bfloat16 *bh, *bl;
    const float *bias, *eps;
    float *stats, *C;
    int M;
};

__global__ __launch_bounds__(512)
void gine_gemm_pair(GineP Pa, GineP Pc) {
    constexpr int SMO_BL = SMO_BH + 256 * 256;
    const bool isA = blockIdx.x < GAC;
    const GineP P = isA ? Pa : Pc;
    const int m0 = (isA ? blockIdx.x : blockIdx.x - GAC) * 128;

    extern __shared__ char smem[];
    uint32_t sb = smem_u32(smem);
    const int tid = threadIdx.x;
    const int wid = tid >> 5;
    const int lid = tid & 31;
    const int wm = wid & 3;
    const int wn = wid >> 2;

    float* bias_s = reinterpret_cast<float*>(smem);
    if (tid < 256) bias_s[tid] = P.bias[tid];

    const float ef = 1.0f + *P.eps;

    float acc[2][8][4];
#pragma unroll
    for (int mt = 0; mt < 2; mt++)
#pragma unroll
        for (int nt = 0; nt < 8; nt++)
#pragma unroll
            for (int j = 0; j < 4; j++) acc[mt][nt][j] = 0.0f;

#pragma unroll
    for (int it = 0; it < 8; it++) {
        int idx = tid + it * 512;
        int n = idx >> 4;
        int ch = idx & 15;
        uint32_t off = n * 256 + ((ch ^ (n & 7)) << 4);
        cp16(sb + SMO_BH + off, P.bh + (size_t)n * 128 + ch * 8);
        cp16(sb + SMO_BL + off, P.bl + (size_t)n * 128 + ch * 8);
    }
    asm volatile("cp.async.commit_group;" ::: "memory");

#pragma unroll
    for (int it = 0; it < 8; it++) {
        int idx = tid + it * 512;
        int r = idx >> 5;
        int c4 = (idx & 31) * 4;
        int gr = m0 + r;
        float4 v = make_float4(0.f, 0.f, 0.f, 0.f);
        if (gr < P.M) {
            float4 a = *reinterpret_cast<const float4*>(P.A0 + (size_t)gr * 128 + c4);
            float4 g = *reinterpret_cast<const float4*>(P.A1 + (size_t)gr * 128 + c4);
            v.x = fmaf(ef, a.x, g.x); v.y = fmaf(ef, a.y, g.y);
            v.z = fmaf(ef, a.z, g.z); v.w = fmaf(ef, a.w, g.w);
        }
        uint32_t bx = __float_as_uint(v.x), by = __float_as_uint(v.y);
        uint32_t bz = __float_as_uint(v.z), bw = __float_as_uint(v.w);
        uint2 hp, lp;
        hp.x = __byte_perm(bx, by, 0x7632);
        hp.y = __byte_perm(bz, bw, 0x7632);
        lp.x = pack_lo_bf16(v.x - __uint_as_float(bx & 0xFFFF0000u),
                            v.y - __uint_as_float(by & 0xFFFF0000u));
        lp.y = pack_lo_bf16(v.z - __uint_as_float(bz & 0xFFFF0000u),
                            v.w - __uint_as_float(bw & 0xFFFF0000u));
        uint32_t off = r * 256 + (((c4 >> 3) ^ (r & 7)) << 4) + ((c4 & 4) << 1);
        *reinterpret_cast<uint2*>(smem + SMO_AH + off) = hp;
        *reinterpret_cast<uint2*>(smem + SMO_AL + off) = lp;
    }
    asm volatile("cp.async.wait_group 0;" ::: "memory");
    __syncthreads();

    const int arow = wm * 32 + (lid & 15);
    const int akp = lid >> 4;
    const int bn = wn * 64 + (lid & 7) + ((lid >> 4) << 3);
    const int bkp = (lid >> 3) & 1;
#pragma unroll
    for (int ks = 0; ks < 8; ks++) {
        uint32_t ah[2][4], al[2][4];
#pragma unroll
        for (int mt = 0; mt < 2; mt++) {
            int r = arow + mt * 16;
            uint32_t ch = (uint32_t)((ks * 2 + akp) ^ (r & 7));
            uint32_t off = r * 256 + (ch << 4);
            ldm_x4(ah[mt], sb + SMO_AH + off);
            ldm_x4(al[mt], sb + SMO_AL + off);
        }
#pragma unroll
        for (int np = 0; np < 4; np++) {
            int n = bn + np * 16;
            uint32_t ch = (uint32_t)((ks * 2 + bkp) ^ (n & 7));
            uint32_t off = n * 256 + (ch << 4);
            uint32_t bh[4], bl[4];
            ldm_x4(bh, sb + SMO_BH + off);
            ldm_x4(bl, sb + SMO_BL + off);
#pragma unroll
            for (int mt = 0; mt < 2; mt++) {
#pragma unroll
                for (int sn = 0; sn < 2; sn++) {
                    float* c = acc[mt][np * 2 + sn];
                    mma16816(c, ah[mt], bh + sn * 2);
                    mma16816(c, ah[mt], bl + sn * 2);
                    mma16816(c, al[mt], bh + sn * 2);
                }
            }
        }
    }

    // epilogue + fused column stats
    const int g = lid >> 2;
    const int tig = lid & 3;
#pragma unroll
    for (int nt = 0; nt < 8; nt++) {
        int nl = wn * 64 + nt * 8 + 2 * tig;
        float b0 = bias_s[nl], b1 = bias_s[nl + 1];
        float s0 = 0.f, s1 = 0.f, q0 = 0.f, q1 = 0.f;
#pragma unroll
        for (int mt = 0; mt < 2; mt++) {
            int m = m0 + wm * 32 + mt * 16 + g;
            if (m < P.M) {
                float ox = acc[mt][nt][0] + b0, oy = acc[mt][nt][1] + b1;
                *reinterpret_cast<float2*>(P.C + (size_t)m * PD + nl) = make_float2(ox, oy);
                s0 += ox; s1 += oy; q0 += ox * ox; q1 += oy * oy;
            }
            if (m + 8 < P.M) {
                float ox = acc[mt][nt][2] + b0, oy = acc[mt][nt][3] + b1;
                *reinterpret_cast<float2*>(P.C + (size_t)(m + 8) * PD + nl) = make_float2(ox, oy);
                s0 += ox; s1 += oy; q0 += ox * ox; q1 += oy * oy;
            }
        }
#pragma unroll
        for (int d = 4; d < 32; d <<= 1) {
            s0 += __shfl_xor_sync(0xFFFFFFFFu, s0, d);
            s1 += __shfl_xor_sync(0xFFFFFFFFu, s1, d);
            q0 += __shfl_xor_sync(0xFFFFFFFFu, q0, d);
            q1 += __shfl_xor_sync(0xFFFFFFFFu, q1, d);
        }
        if (g == 0) {
            atomicAdd(P.stats + nl, s0);
            atomicAdd(P.stats + nl + 1, s1);
            atomicAdd(P.stats + PD + nl, q0);
            atomicAdd(P.stats + PD + nl + 1, q1);
        }
    }
}

// ---------------- fused SAGE + MERGE pair -------------------------------------------
#define F_BIAS1 0
#define F_BIAS2 1024
#define F_SCALE 1536
#define F_SHIFT 2560
#define F_A1H   4096
#define F_A1L   36864
#define F_B1H   69632
#define F_B1L   135168
#define F_A2H   F_B1H
#define F_A2L   F_B1L
#define F_B2H   F_A1H
#define F_B2L   F_A1L
#define SMEM_FUSED 200704

struct FusedP {
    const float *aggm, *xdst, *cnt;
    const __nv_bfloat16 *b1h, *b1l;
    const float *sbl, *sbr, *pre, *scale, *shift;
    const __nv_bfloat16 *b2h, *b2l;
    const float *mbias;
    float *C;
    int M;
};

__global__ __launch_bounds__(512)
void sage_merge_pair(FusedP Pa, FusedP Pc) {
    const bool isA = blockIdx.x < GAC;
    const FusedP P = isA ? Pa : Pc;
    const int m0 = (isA ? blockIdx.x : blockIdx.x - GAC) * 128;

    extern __shared__ char smem[];
    uint32_t sb = smem_u32(smem);
    const int tid = threadIdx.x;
    const int wid = tid >> 5;
    const int lid = tid & 31;

    float* bias1_s = reinterpret_cast<float*>(smem + F_BIAS1);
    float* bias2_s = reinterpret_cast<float*>(smem + F_BIAS2);
    float* scale_s = reinterpret_cast<float*>(smem + F_SCALE);
    float* shift_s = reinterpret_cast<float*>(smem + F_SHIFT);
    if (tid < 256) {
        bias1_s[tid] = P.sbl[tid] + P.sbr[tid];
        scale_s[tid] = P.scale[tid];
        shift_s[tid] = P.shift[tid];
    } else if (tid < 384) {
        bias2_s[tid - 256] = P.mbias[tid - 256];
    }

    // ===== Phase 1: SAGE GEMM, warps 4m x 4n =====
    const int wm = wid & 3;
    const int wn = wid >> 2;
    float acc[2][8][4];
#pragma unroll
    for (int mt = 0; mt < 2; mt++)
#pragma unroll
        for (int nt = 0; nt < 8; nt++)
#pragma unroll
            for (int j = 0; j < 4; j++) acc[mt][nt][j] = 0.0f;

    for (int kk = 0; kk < 256; kk += 128) {
#pragma unroll
        for (int it = 0; it < 8; it++) {
            int idx = tid + it * 512;
            int n = idx >> 4;
            int ch = idx & 15;
            uint32_t off = n * 256 + ((ch ^ (n & 7)) << 4);
            cp16(sb + F_B1H + off, P.b1h + (size_t)n * 256 + kk + ch * 8);
            cp16(sb + F_B1L + off, P.b1l + (size_t)n * 256 + kk + ch * 8);
        }
        asm volatile("cp.async.commit_group;" ::: "memory");

#pragma unroll
        for (int it = 0; it < 8; it++) {
            int idx = tid + it * 512;
            int r = idx >> 5;
            int c4 = (idx & 31) * 4;
            int gr = m0 + r;
            int gk = kk + c4;
            float4 v = make_float4(0.f, 0.f, 0.f, 0.f);
            if (gr < P.M) {
                if (gk < 128) {
                    float4 a = *reinterpret_cast<const float4*>(P.aggm + (size_t)gr * 128 + gk);
                    float inv = __frcp_rn(fmaxf(P.cnt[gr], 1.0f));
                    v.x = a.x * inv; v.y = a.y * inv; v.z = a.z * inv; v.w = a.w * inv;
                } else {
                    v = *reinterpret_cast<const float4*>(P.xdst + (size_t)gr * 128 + (gk - 128));
                }
            }
            uint32_t bx = __float_as_uint(v.x), by = __float_as_uint(v.y);
            uint32_t bz = __float_as_uint(v.z), bw = __float_as_uint(v.w);
            uint2 hp, lp;
            hp.x = __byte_perm(bx, by, 0x7632);
            hp.y = __byte_perm(bz, bw, 0x7632);
            lp.x = pack_lo_bf16(v.x - __uint_as_float(bx & 0xFFFF0000u),
                                v.y - __uint_as_float(by & 0xFFFF0000u));
            lp.y = pack_lo_bf16(v.z - __uint_as_float(bz & 0xFFFF0000u),
                                v.w - __uint_as_float(bw & 0xFFFF0000u));
            uint32_t off = r * 256 + (((c4 >> 3) ^ (r & 7)) << 4) + ((c4 & 4) << 1);
            *reinterpret_cast<uint2*>(smem + F_A1H + off) = hp;
            *reinterpret_cast<uint2*>(smem + F_A1L + off) = lp;
        }
        asm volatile("cp.async.wait_group 0;" ::: "memory");
        __syncthreads();

        const int arow = wm * 32 + (lid & 15);
        const int akp = lid >> 4;
        const int bn = wn * 64 + (lid & 7) + ((lid >> 4) << 3);
        const int bkp = (lid >> 3) & 1;
#pragma unroll
        for (int ks = 0; ks < 8; ks++) {
            uint32_t ah[2][4], al[2][4];
#pragma unroll
            for (int mt = 0; mt < 2; mt++) {
                int r = arow + mt * 16;
                uint32_t ch = (uint32_t)((ks * 2 + akp) ^ (r & 7));
                uint32_t off = r * 256 + (ch << 4);
                ldm_x4(ah[mt], sb + F_A1H + off);
                ldm_x4(al[mt], sb + F_A1L + off);
            }
#pragma unroll
            for (int np = 0; np < 4; np++) {
                int n = bn + np * 16;
                uint32_t ch = (uint32_t)((ks * 2 + bkp) ^ (n & 7));
                uint32_t off = n * 256 + (ch << 4);
                uint32_t bh[4], blx[4];
                ldm_x4(bh, sb + F_B1H + off);
                ldm_x4(blx, sb + F_B1L + off);
#pragma unroll
                for (int mt = 0; mt < 2; mt++) {
#pragma unroll
                    for (int sn = 0; sn < 2; sn++) {
                        float* c = acc[mt][np * 2 + sn];
                        mma16816(c, ah[mt], bh + sn * 2);
                        mma16816(c, ah[mt], blx + sn * 2);
                        mma16816(c, al[mt], bh + sn * 2);
                    }
                }
            }
        }
        __syncthreads();
    }

    // ===== Phase 2: A2 = relu(pre*scale+shift) + S -> smem split bf16 =====
    {
        const int g = lid >> 2;
        const int tig = lid & 3;
#pragma unroll
        for (int nt = 0; nt < 8; nt++) {
            int nl = wn * 64 + nt * 8 + 2 * tig;
            float b0 = bias1_s[nl], b1 = bias1_s[nl + 1];
            float sc0 = scale_s[nl], sc1 = scale_s[nl + 1];
            float sh0 = shift_s[nl], sh1 = shift_s[nl + 1];
#pragma unroll
            for (int mt = 0; mt < 2; mt++) {
#pragma unroll
                for (int half = 0; half < 2; half++) {
                    int r = wm * 32 + mt * 16 + g + half * 8;
                    int m = m0 + r;
                    float ax = 0.f, ay = 0.f;
                    if (m < P.M) {
                        float2 p = *reinterpret_cast<const float2*>(P.pre + (size_t)m * PD + nl);
                        ax = fmaxf(fmaf(p.x, sc0, sh0), 0.f) + acc[mt][nt][half * 2 + 0] + b0;
                        ay = fmaxf(fmaf(p.y, sc1, sh1), 0.f) + acc[mt][nt][half * 2 + 1] + b1;
                    }
                    uint32_t bx = __float_as_uint(ax), by = __float_as_uint(ay);
                    uint32_t hp = __byte_perm(bx, by, 0x7632);
                    uint32_t lp = pack_lo_bf16(ax - __uint_as_float(bx & 0xFFFF0000u),
                                               ay - __uint_as_float(by & 0xFFFF0000u));
                    uint32_t off = r * 512 + (((nl >> 3) ^ (r & 7)) << 4) + (nl & 7) * 2;
                    *reinterpret_cast<uint32_t*>(smem + F_A2H + off) = hp;
                    *reinterpret_cast<uint32_t*>(smem + F_A2L + off) = lp;
                }
            }
        }
    }
    __syncthreads();

    // ===== Phase 3: merge GEMM from smem A2, warps 8m x 2n =====
    const int wm2 = wid & 7;
    const int wn2 = wid >> 3;
    float acc2[8][4];
#pragma unroll
    for (int nt = 0; nt < 8; nt++)
#pragma unroll
        for (int j = 0; j < 4; j++) acc2[nt][j] = 0.0f;

    const int arow2 = wm2 * 16 + (lid & 15);
    const int akp2 = lid >> 4;
    const int bn2 = wn2 * 64 + (lid & 7) + ((lid >> 4) << 3);
    const int bkp2 = (lid >> 3) & 1;

    for (int kk = 0; kk < 256; kk += 128) {
#pragma unroll
        for (int it = 0; it < 4; it++) {
            int idx = tid + it * 512;
            int n = idx >> 4;
            int ch = idx & 15;
            uint32_t off = n * 256 + ((ch ^ (n & 7)) << 4);
            cp16(sb + F_B2H + off, P.b2h + (size_t)n * 256 + kk + ch * 8);
            cp16(sb + F_B2L + off, P.b2l + (size_t)n * 256 + kk + ch * 8);
        }
        asm volatile("cp.async.commit_group;" ::: "memory");
        asm volatile("cp.async.wait_group 0;" ::: "memory");
        __syncthreads();

#pragma unroll
        for (int ks = 0; ks < 8; ks++) {
            uint32_t ah[4], al[4];
            {
                int r = arow2;
                uint32_t ch = (uint32_t)(((kk >> 3) + ks * 2 + akp2) ^ (r & 7));
                uint32_t off = r * 512 + (ch << 4);
                ldm_x4(ah, sb + F_A2H + off);
                ldm_x4(al, sb + F_A2L + off);
            }
#pragma unroll
            for (int np = 0; np < 4; np++) {
                int n = bn2 + np * 16;
                uint32_t ch = (uint32_t)((ks * 2 + bkp2) ^ (n & 7));
                uint32_t off = n * 256 + (ch << 4);
                uint32_t bh[4], blx[4];
                ldm_x4(bh, sb + F_B2H + off);
                ldm_x4(blx, sb + F_B2L + off);
#pragma unroll
                for (int sn = 0; sn < 2; sn++) {
                    float* c = acc2[np * 2 + sn];
                    mma16816(c, ah, bh + sn * 2);
                    mma16816(c, ah, blx + sn * 2);
                    mma16816(c, al, bh + sn * 2);
                }
            }
        }
        __syncthreads();
    }

    // epilogue
    {
        const int g = lid >> 2;
        const int tig = lid & 3;
#pragma unroll
        for (int nt = 0; nt < 8; nt++) {
            int nl = wn2 * 64 + nt * 8 + 2 * tig;
            float b0 = bias2_s[nl], b1 = bias2_s[nl + 1];
            int m = m0 + wm2 * 16 + g;
            if (m < P.M) {
                *reinterpret_cast<float2*>(P.C + (size_t)m * HD + nl) =
                    make_float2(acc2[nt][0] + b0, acc2[nt][1] + b1);
            }
            if (m + 8 < P.M) {
                *reinterpret_cast<float2*>(P.C + (size_t)(m + 8) * HD + nl) =
                    make_float2(acc2[nt][2] + b0, acc2[nt][3] + b1);
            }
        }
    }
}

// -----------------------------------------------------------------------------------
extern "C" void kernel_launch(void* const* d_in, const int* in_sizes, int n_in,
                              void* d_out, int out_size) {
    const float* x         = (const float*)d_in[0];
    const float* edge_attr = (const float*)d_in[1];
    const float* x_cl      = (const float*)d_in[2];
    const float* c2c_ea    = (const float*)d_in[3];

    int pbase, ebase;
    if (in_sizes[4] == 2 * EA) { ebase = 4; pbase = 8; }
    else                       { pbase = 4; ebase = 26; }

    const int* ei_a   = (const int*)d_in[ebase + 0];
    const int* ei_c2c = (const int*)d_in[ebase + 1];
    const int* ei_a2c = (const int*)d_in[ebase + 2];
    const int* ei_c2a = (const int*)d_in[ebase + 3];

    const float* atom_eps   = (const float*)d_in[pbase + 0];
    const float* atom_W     = (const float*)d_in[pbase + 1];
    const float* atom_b     = (const float*)d_in[pbase + 2];
    const float* atom_gamma = (const float*)d_in[pbase + 3];
    const float* atom_beta  = (const float*)d_in[pbase + 4];
    const float* cl_eps     = (const float*)d_in[pbase + 5];
    const float* cl_W       = (const float*)d_in[pbase + 6];
    const float* cl_b       = (const float*)d_in[pbase + 7];
    const float* cl_gamma   = (const float*)d_in[pbase + 8];
    const float* cl_beta    = (const float*)d_in[pbase + 9];
    const float* a2c_Wl     = (const float*)d_in[pbase + 10];
    const float* a2c_bl     = (const float*)d_in[pbase + 11];
    const float* a2c_Wr     = (const float*)d_in[pbase + 12];
    const float* a2c_br     = (const float*)d_in[pbase + 13];
    const float* c2a_Wl     = (const float*)d_in[pbase + 14];
    const float* c2a_bl     = (const float*)d_in[pbase + 15];
    const float* c2a_Wr     = (const float*)d_in[pbase + 16];
    const float* c2a_br     = (const float*)d_in[pbase + 17];
    const float* merge_atom_W = (const float*)d_in[pbase + 18];
    const float* merge_atom_b = (const float*)d_in[pbase + 19];
    const float* merge_cl_W   = (const float*)d_in[pbase + 20];
    const float* merge_cl_b   = (const float*)d_in[pbase + 21];

    float* out = (float*)d_out;

    float *p_zero, *p_pre_atom, *p_pre_cl;
    float *p_scale_atom, *p_shift_atom, *p_scale_cl, *p_shift_cl;
    __nv_bfloat16 *p_Bt_hi, *p_Bt_lo;
    cudaGetSymbolAddress((void**)&p_zero, g_zero);
    cudaGetSymbolAddress((void**)&p_pre_atom, g_pre_atom);
    cudaGetSymbolAddress((void**)&p_pre_cl, g_pre_cl);
    cudaGetSymbolAddress((void**)&p_scale_atom, g_scale_atom);
    cudaGetSymbolAddress((void**)&p_shift_atom, g_shift_atom);
    cudaGetSymbolAddress((void**)&p_scale_cl, g_scale_cl);
    cudaGetSymbolAddress((void**)&p_shift_cl, g_shift_cl);
    cudaGetSymbolAddress((void**)&p_Bt_hi, g_Bt_hi);
    cudaGetSymbolAddress((void**)&p_Bt_lo, g_Bt_lo);

    float* p_agg_atom  = p_zero + Z_AGG_ATOM;
    float* p_agg_cl    = p_zero + Z_AGG_CL;
    float* p_aggm_c2a  = p_zero + Z_AGGM_C2A;
    float* p_aggm_a2c  = p_zero + Z_AGGM_A2C;
    float* p_cnt_c2a   = p_zero + Z_CNT_C2A;
    float* p_cnt_a2c   = p_zero + Z_CNT_A2C;
    float* p_stats_atom = p_zero + Z_STATS_A;
    float* p_stats_cl   = p_zero + Z_STATS_C;

    // one memset for all zeroed scratch
    cudaMemsetAsync(p_zero, 0, (size_t)Z_TOTAL * 4, 0);

    cudaFuncSetAttribute((const void*)gine_gemm_pair,
                         cudaFuncAttributeMaxDynamicSharedMemorySize, SMEM_GINE);
    cudaFuncSetAttribute((const void*)sage_merge_pair,
                         cudaFuncAttributeMaxDynamicSharedMemorySize, SMEM_FUSED);

    // ---- mega scatter + wsplit (one launch) ----
    {
        MegaArgs A;
        A.x = x; A.ea = edge_attr; A.xcl = x_cl; A.cea = c2c_ea;
        A.ei_a = ei_a; A.ei_c = ei_c2c; A.ei_a2c = ei_a2c; A.ei_c2a = ei_c2a;
        A.agg_atom = p_agg_atom; A.agg_cl = p_agg_cl;
        A.aggm_a2c = p_aggm_a2c; A.cnt_a2c = p_cnt_a2c;
        A.aggm_c2a = p_aggm_c2a; A.cnt_c2a = p_cnt_c2a;
        A.wsrc[0] = atom_W;  A.wsrc[1] = cl_W;
        A.wsrc[2] = c2a_Wl;  A.wsrc[3] = c2a_Wr;
        A.wsrc[4] = a2c_Wl;  A.wsrc[5] = a2c_Wr;
        A.wsrc[6] = merge_atom_W; A.wsrc[7] = merge_cl_W;
        A.oh = p_Bt_hi; A.ol = p_Bt_lo;
        mega_scatter<<<SCATTER_BLOCKS + WSPLIT_BLOCKS, 256>>>(A);
    }

    // ---- GINE GEMM pair (pre-BN, fused column stats) ----
    {
        GineP Pa{x, p_agg_atom, p_Bt_hi + OFF_GA, p_Bt_lo + OFF_GA,
                 atom_b, atom_eps, p_stats_atom, p_pre_atom, NATOM};
        GineP Pc{x_cl, p_agg_cl, p_Bt_hi + OFF_GC, p_Bt_lo + OFF_GC,
                 cl_b, cl_eps, p_stats_cl, p_pre_cl, NCL};
        gine_gemm_pair<<<GAC + GCC, 512, SMEM_GINE>>>(Pa, Pc);
    }

    bn_finalize2<<<1, 512>>>(p_stats_atom, p_stats_cl, atom_gamma, atom_beta,
                             cl_gamma, cl_beta, p_scale_atom, p_shift_atom,
                             p_scale_cl, p_shift_cl);

    // ---- fused SAGE + MERGE pair ----
    {
        FusedP Pa{p_aggm_c2a, x, p_cnt_c2a,
                  p_Bt_hi + OFF_SA, p_Bt_lo + OFF_SA, c2a_bl, c2a_br,
                  p_pre_atom, p_scale_atom, p_shift_atom,
                  p_Bt_hi + OFF_MA, p_Bt_lo + OFF_MA, merge_atom_b, out, NATOM};
        FusedP Pc{p_aggm_a2c, x_cl, p_cnt_a2c,
                  p_Bt_hi + OFF_SC, p_Bt_lo + OFF_SC, a2c_bl, a2c_br,
                  p_pre_cl, p_scale_cl, p_shift_cl,
                  p_Bt_hi + OFF_MC, p_Bt_lo + OFF_MC, merge_cl_b,
                  out + (size_t)NATOM * HD, NCL};
        sage_merge_pair<<<GAC + GCC, 512, SMEM_FUSED>>>(Pa, Pc);
    }
}